// round 5
// baseline (speedup 1.0000x reference)
#include <cuda_runtime.h>
#include <cuda_bf16.h>

#define D 8192
#define BATCH 4096
#define ROWS_PER_BLOCK 16
#define GRID_X (D / 1024)                       // 8
#define GRID_Y (BATCH / ROWS_PER_BLOCK)         // 256
#define NBLK   (GRID_X * GRID_Y)                // 2048

// Device scratch + sync state (allocation-free rule: __device__ globals).
__device__ float d_z[D];      // after high-bit FWHT stages
__device__ float d_w[D];      // final weight row
__device__ int   d_ctrA;      // phase-A completions (0..8)
__device__ int   d_ctrB;      // phase-B completions (0..8)
__device__ int   d_done;      // finished blocks (for counter reset)

__device__ __forceinline__ int ld_vol(const int* p) {
    int v;
    asm volatile("ld.volatile.global.s32 %0, [%1];" : "=r"(v) : "l"(p));
    return v;
}

// ---------------------------------------------------------------------------
// Single fused kernel.
//   w[j] = s1[0] * s2[j] * FWHT(g_mu + softplus(g_rho)*eps)[j]   (j = row 0 of
//   the WHVI matrix), then out[b][j] = x[b] * w[j].
// Element index j = g*128 + low (g: 6 bits, low: 7 bits). High-bit stages
// (strides 128..4096) act on g only; low-bit stages (1..64) act on low only,
// so phase A and phase B decompose cleanly (validated rounds 3-4).
// ---------------------------------------------------------------------------
__global__ __launch_bounds__(256)
void whvi_fused_kernel(const float* __restrict__ x,
                       const float* __restrict__ s1,
                       const float* __restrict__ s2,
                       const float* __restrict__ g_mu,
                       const float* __restrict__ g_rho,
                       const float* __restrict__ eps,
                       float* __restrict__ out) {
    __shared__ float sm[64 * 17];
    const int t  = threadIdx.x;
    const int bx = blockIdx.x;
    const int by = blockIdx.y;

    // ---- consumer prologue: overlap x loads with the producer chain ----
    const int b0 = by * ROWS_PER_BLOCK;
    float xs[ROWS_PER_BLOCK];
    #pragma unroll
    for (int q = 0; q < ROWS_PER_BLOCK; q++)
        xs[q] = __ldg(x + b0 + q);

    // ======================= producer path (8 blocks) ======================
    if (by == 0) {
        // ---- phase A: softplus + high-bit stages for lows [bx*16, bx*16+16)
        const int g    = t >> 2;                  // 0..63
        const int l4   = (t & 3) * 4;             // 0,4,8,12
        const int base = g * 128 + bx * 16 + l4;

        const float s10 = __ldg(s1);
        float4 mu = *(const float4*)(g_mu  + base);
        float4 rh = *(const float4*)(g_rho + base);
        float4 ep = *(const float4*)(eps   + base);

        float v[4] = {rh.x, rh.y, rh.z, rh.w};
        float m[4] = {mu.x, mu.y, mu.z, mu.w};
        float e[4] = {ep.x, ep.y, ep.z, ep.w};
        #pragma unroll
        for (int i = 0; i < 4; i++) {
            float sp = fmaxf(v[i], 0.0f) + __logf(1.0f + __expf(-fabsf(v[i])));
            sm[g * 17 + l4 + i] = s10 * fmaf(sp, e[i], m[i]);
        }
        __syncthreads();

        #pragma unroll
        for (int s = 0; s < 6; s++) {             // strides 1..32 in g
            const int h = 1 << s;
            #pragma unroll
            for (int bb = 0; bb < 2; bb++) {
                int bi = t + bb * 256;            // butterfly 0..511
                int l  = bi & 15;
                int gi = bi >> 4;
                int ga = ((gi & ~(h - 1)) << 1) | (gi & (h - 1));
                int gb = ga + h;
                float a = sm[ga * 17 + l], b = sm[gb * 17 + l];
                sm[ga * 17 + l] = a + b;
                sm[gb * 17 + l] = a - b;
            }
            __syncthreads();
        }

        float4 oz;
        oz.x = sm[g * 17 + l4 + 0];
        oz.y = sm[g * 17 + l4 + 1];
        oz.z = sm[g * 17 + l4 + 2];
        oz.w = sm[g * 17 + l4 + 3];
        *(float4*)(d_z + base) = oz;

        __threadfence();
        __syncthreads();
        if (t == 0) atomicAdd(&d_ctrA, 1);

        // ---- phase B: low-bit stages for groups g2 in [bx*8, bx*8+8) ------
        const int lane  = t & 31;
        const int w     = t >> 5;                 // warp 0..7
        const int g2    = bx * 8 + w;             // 128-group
        const int base2 = g2 * 128 + lane;

        float s2v[4];
        #pragma unroll
        for (int k = 0; k < 4; k++) s2v[k] = __ldg(s2 + base2 + k * 32);

        if (t == 0) { while (ld_vol(&d_ctrA) < 8) { } }
        __syncthreads();
        __threadfence();

        float rr[4];
        #pragma unroll
        for (int k = 0; k < 4; k++) rr[k] = d_z[base2 + k * 32];

        #pragma unroll
        for (int mm = 1; mm <= 16; mm <<= 1) {    // strides 1..16 (lane bits)
            const float sgn = (lane & mm) ? -1.0f : 1.0f;
            #pragma unroll
            for (int k = 0; k < 4; k++) {
                float o = __shfl_xor_sync(0xffffffffu, rr[k], mm);
                rr[k] = fmaf(sgn, rr[k], o);
            }
        }
        { // stride 32 (k bit 0)
            float a0 = rr[0], c0 = rr[1], a1 = rr[2], c1 = rr[3];
            rr[0] = a0 + c0; rr[1] = a0 - c0;
            rr[2] = a1 + c1; rr[3] = a1 - c1;
        }
        { // stride 64 (k bit 1)
            float a0 = rr[0], c0 = rr[2], a1 = rr[1], c1 = rr[3];
            rr[0] = a0 + c0; rr[2] = a0 - c0;
            rr[1] = a1 + c1; rr[3] = a1 - c1;
        }
        #pragma unroll
        for (int k = 0; k < 4; k++) d_w[base2 + k * 32] = s2v[k] * rr[k];

        __threadfence();
        __syncthreads();
        if (t == 0) atomicAdd(&d_ctrB, 1);
    }

    // ======================= wait for w, then stream =======================
    if (t == 0) {
        while (ld_vol(&d_ctrB) < 8) { __nanosleep(64); }
    }
    __syncthreads();
    __threadfence();

    const int jbase = bx * 1024 + t * 4;
    const float4 w4 = *(const float4*)(d_w + jbase);

    #pragma unroll
    for (int q = 0; q < ROWS_PER_BLOCK; q++) {
        float xv = xs[q];
        float4 o = make_float4(xv * w4.x, xv * w4.y, xv * w4.z, xv * w4.w);
        // 134 MB output, never re-read -> streaming (evict-first) store
        __stcs((float4*)(out + (size_t)(b0 + q) * D + jbase), o);
    }

    // ---- generation-safe counter reset: last block of this launch ----
    __syncthreads();
    if (t == 0) {
        int dn = atomicAdd(&d_done, 1);
        if (dn == NBLK - 1) {
            atomicExch(&d_ctrA, 0);
            atomicExch(&d_ctrB, 0);
            atomicExch(&d_done, 0);
        }
    }
}

extern "C" void kernel_launch(void* const* d_in, const int* in_sizes, int n_in,
                              void* d_out, int out_size) {
    const float* x     = (const float*)d_in[0];  // (4096, 1)
    const float* s1    = (const float*)d_in[1];  // (8192,)
    const float* s2    = (const float*)d_in[2];  // (8192,)
    const float* g_mu  = (const float*)d_in[3];  // (8192,)
    const float* g_rho = (const float*)d_in[4];  // (8192,)
    const float* eps   = (const float*)d_in[5];  // (8192,)
    float* out = (float*)d_out;                  // (4096, 8192) f32

    dim3 grid(GRID_X, GRID_Y);                   // (8, 256)
    whvi_fused_kernel<<<grid, 256>>>(x, s1, s2, g_mu, g_rho, eps, out);
}

// round 6
// speedup vs baseline: 1.1251x; 1.1251x over previous
#include <cuda_runtime.h>
#include <cuda_bf16.h>

#define D 8192
#define BATCH 4096

// Intermediate z = s1[0] * (H_64 (x) I_128) g_tilde  (high-bit FWHT stages done).
__device__ float d_z[D];

// ---------------------------------------------------------------------------
// Kernel 1: high-bit stages (strides 128,256,...,4096) = 128 independent
// 64-point FWHTs over index sets {g*128 + low : g=0..63}, one warp per low.
// 16 blocks x 256 threads (128 warps). lane = g bits 0..4 (shfl), g bit 5 local.
// Also folds in g_tilde = g_mu + softplus(g_rho)*eps and the s1[0] scale.
// ---------------------------------------------------------------------------
__global__ __launch_bounds__(256, 1)
void stageA_kernel(const float* __restrict__ s1,
                   const float* __restrict__ g_mu,
                   const float* __restrict__ g_rho,
                   const float* __restrict__ eps) {
#if __CUDA_ARCH__ >= 900
    cudaTriggerProgrammaticLaunchCompletion();   // let outer's prologue start now
#endif
    const int lane = threadIdx.x & 31;
    const int wi   = threadIdx.x >> 5;
    const int low  = blockIdx.x * 8 + wi;        // 0..127
    const float s10 = __ldg(s1);

    const int e0 = lane * 128 + low;             // g = lane
    const int e1 = e0 + 32 * 128;                // g = lane + 32

    float r0, r1;
    {
        float v0 = __ldg(g_rho + e0), v1 = __ldg(g_rho + e1);
        float sp0 = fmaxf(v0, 0.0f) + __logf(1.0f + __expf(-fabsf(v0)));
        float sp1 = fmaxf(v1, 0.0f) + __logf(1.0f + __expf(-fabsf(v1)));
        r0 = s10 * fmaf(sp0, __ldg(eps + e0), __ldg(g_mu + e0));
        r1 = s10 * fmaf(sp1, __ldg(eps + e1), __ldg(g_mu + e1));
    }

    // g bits 0..4 via shfl.xor (strides 128..2048)
    #pragma unroll
    for (int m = 1; m <= 16; m <<= 1) {
        const float sgn = (lane & m) ? -1.0f : 1.0f;
        float o0 = __shfl_xor_sync(0xffffffffu, r0, m);
        float o1 = __shfl_xor_sync(0xffffffffu, r1, m);
        r0 = fmaf(sgn, r0, o0);
        r1 = fmaf(sgn, r1, o1);
    }
    // g bit 5 (stride 4096): local butterfly
    float a = r0, b = r1;
    d_z[e0] = a + b;
    d_z[e1] = a - b;
}

// ---------------------------------------------------------------------------
// Kernel 2: finish low-bit FWHT stages (strides 1..64, confined to 128-groups)
// on this block's 1024-column chunk, apply s2, then stream the rank-1 outer
// product: out[b][j] = x[b] * w[j].   grid (8, 256), 256 threads, 16 rows/blk.
// PDL: x and s2 are preloaded BEFORE the grid dependency sync.
// Stores are DEFAULT policy (evict-normal): the output buffer is reused every
// graph replay and nearly fits in the ~126MB L2, so keeping lines resident
// avoids compulsory DRAM writebacks that evict-first (__stcs) was forcing.
// ---------------------------------------------------------------------------
#define ROWS_PER_BLOCK 16

__global__ __launch_bounds__(256)
void outer_kernel(const float* __restrict__ x,
                  const float* __restrict__ s2,
                  float* __restrict__ out) {
    __shared__ float sw[1024];
    const int tid  = threadIdx.x;
    const int lane = tid & 31;
    const int r    = tid >> 5;                    // warp = 128-group within chunk
    const int jb   = blockIdx.x * 1024;
    const int base = jb + r * 128 + lane;         // elems base + k*32, k=0..3
    const int b0   = blockIdx.y * ROWS_PER_BLOCK;

    // ---- prologue independent of kernel 1 ----
    float xs[ROWS_PER_BLOCK];
    #pragma unroll
    for (int q = 0; q < ROWS_PER_BLOCK; q++)
        xs[q] = __ldg(x + b0 + q);                // broadcast loads

    float s2v[4];
    #pragma unroll
    for (int k = 0; k < 4; k++)
        s2v[k] = __ldg(s2 + base + k * 32);

#if __CUDA_ARCH__ >= 900
    cudaGridDependencySynchronize();              // wait for d_z
#endif

    // ---- load z chunk: low bits: lane = bits 0..4, k = bits 5..6 ----
    float rr[4];
    #pragma unroll
    for (int k = 0; k < 4; k++)
        rr[k] = d_z[base + k * 32];

    // strides 1..16 via shfl.xor on lane bits
    #pragma unroll
    for (int m = 1; m <= 16; m <<= 1) {
        const float sgn = (lane & m) ? -1.0f : 1.0f;
        #pragma unroll
        for (int k = 0; k < 4; k++) {
            float o = __shfl_xor_sync(0xffffffffu, rr[k], m);
            rr[k] = fmaf(sgn, rr[k], o);
        }
    }
    // stride 32 (k bit 0): (0,1), (2,3)
    {
        float a0 = rr[0], c0 = rr[1], a1 = rr[2], c1 = rr[3];
        rr[0] = a0 + c0; rr[1] = a0 - c0;
        rr[2] = a1 + c1; rr[3] = a1 - c1;
    }
    // stride 64 (k bit 1): (0,2), (1,3)
    {
        float a0 = rr[0], c0 = rr[2], a1 = rr[1], c1 = rr[3];
        rr[0] = a0 + c0; rr[2] = a0 - c0;
        rr[1] = a1 + c1; rr[3] = a1 - c1;
    }

    // apply s2 and transpose through smem so each thread owns 4 contiguous cols
    #pragma unroll
    for (int k = 0; k < 4; k++)
        sw[r * 128 + k * 32 + lane] = s2v[k] * rr[k];
    __syncthreads();

    const float4 w4 = *(const float4*)&sw[tid * 4];
    const int jbase = jb + tid * 4;

    #pragma unroll
    for (int q = 0; q < ROWS_PER_BLOCK; q++) {
        float xv = xs[q];
        float4 o = make_float4(xv * w4.x, xv * w4.y, xv * w4.z, xv * w4.w);
        // Default (evict-normal) store: keep output L2-resident across replays.
        *(float4*)(out + (size_t)(b0 + q) * D + jbase) = o;
    }
}

extern "C" void kernel_launch(void* const* d_in, const int* in_sizes, int n_in,
                              void* d_out, int out_size) {
    const float* x     = (const float*)d_in[0];  // (4096, 1)
    const float* s1    = (const float*)d_in[1];  // (8192,)
    const float* s2    = (const float*)d_in[2];  // (8192,)
    const float* g_mu  = (const float*)d_in[3];  // (8192,)
    const float* g_rho = (const float*)d_in[4];  // (8192,)
    const float* eps   = (const float*)d_in[5];  // (8192,)
    float* out = (float*)d_out;                  // (4096, 8192) f32

    stageA_kernel<<<16, 256>>>(s1, g_mu, g_rho, eps);

    cudaLaunchConfig_t cfg = {};
    cfg.gridDim  = dim3(D / 1024, BATCH / ROWS_PER_BLOCK, 1);  // (8, 256)
    cfg.blockDim = dim3(256, 1, 1);
    cfg.stream   = 0;
    cudaLaunchAttribute attr;
    attr.id = cudaLaunchAttributeProgrammaticStreamSerialization;
    attr.val.programmaticStreamSerializationAllowed = 1;
    cfg.attrs    = &attr;
    cfg.numAttrs = 1;
    cudaLaunchKernelEx(&cfg, outer_kernel, x, s2, out);
}